// round 8
// baseline (speedup 1.0000x reference)
#include <cuda_runtime.h>
#include <cuda_fp16.h>
#include <cstdint>

// Problem constants (match reference_code)
#define NROWS 100001
#define DIM   64
#define NNZ_E 3200000
#define ND    (NROWS * DIM)          // floats per segment
#define ND8   (ND / 8)               // uint4 (8 halves) per fp16 segment
#define ND4   (ND / 4)
#define SCAN_B 1024
#define NBLK  ((NROWS + SCAN_B - 1) / SCAN_B)   // 98

// ---------------------------------------------------------------------------
// Static device scratch. Referenced ONLY inside device code (R6 lesson:
// passing a __device__ symbol as a host-side kernel arg gives garbage).
// ---------------------------------------------------------------------------
__device__ int   g_counts[NROWS];       // histogram, then scatter cursors
__device__ int   g_rowptr[NROWS + 1];   // CSR row pointers (exclusive scan)
__device__ int   g_partials[NBLK];      // scan block totals
__device__ int2  g_meta[NNZ_E];         // CSR-ordered (col, val-bits), 25.6MB
__device__ uint4 g_embh[ND8];           // emb in fp16 (8 halves/uint4), 12.8MB
__device__ uint4 g_e1h[ND8];            // e1  in fp16, 12.8MB

// ---------------------------------------------------------------------------
// K1: prep — e0 = emb (fp32 copy), embh = fp16(emb), zero histogram.
//     One thread handles 8 floats (one uint4 of halves).
// ---------------------------------------------------------------------------
__global__ void prep_kernel(const float4* __restrict__ emb,
                            float4* __restrict__ e0)
{
    int i = blockIdx.x * blockDim.x + threadIdx.x;
    if (i < ND8) {
        float4 a = __ldg(emb + 2 * i);
        float4 b = __ldg(emb + 2 * i + 1);
        e0[2 * i]     = a;
        e0[2 * i + 1] = b;
        __half2 h0 = __floats2half2_rn(a.x, a.y);
        __half2 h1 = __floats2half2_rn(a.z, a.w);
        __half2 h2 = __floats2half2_rn(b.x, b.y);
        __half2 h3 = __floats2half2_rn(b.z, b.w);
        uint4 u;
        u.x = *reinterpret_cast<unsigned*>(&h0);
        u.y = *reinterpret_cast<unsigned*>(&h1);
        u.z = *reinterpret_cast<unsigned*>(&h2);
        u.w = *reinterpret_cast<unsigned*>(&h3);
        g_embh[i] = u;
    }
    if (i < NROWS) g_counts[i] = 0;
    if (i == 0) g_rowptr[NROWS] = NNZ_E;
}

// ---------------------------------------------------------------------------
// K2: histogram of row indices, 4 edges/thread via int4.
// ---------------------------------------------------------------------------
__global__ void hist_kernel(const int4* __restrict__ row4)
{
    int i = blockIdx.x * blockDim.x + threadIdx.x;
    if (i < NNZ_E / 4) {
        int4 r = __ldg(row4 + i);
        atomicAdd(&g_counts[r.x], 1);
        atomicAdd(&g_counts[r.y], 1);
        atomicAdd(&g_counts[r.z], 1);
        atomicAdd(&g_counts[r.w], 1);
    }
}

// ---------------------------------------------------------------------------
// K3a: per-block exclusive scan of counts; block totals to g_partials.
// ---------------------------------------------------------------------------
__global__ void scan1_kernel()
{
    __shared__ int s[SCAN_B];
    int gid = blockIdx.x * SCAN_B + threadIdx.x;
    int v = (gid < NROWS) ? g_counts[gid] : 0;
    s[threadIdx.x] = v;
    __syncthreads();
    #pragma unroll
    for (int off = 1; off < SCAN_B; off <<= 1) {
        int t = (threadIdx.x >= off) ? s[threadIdx.x - off] : 0;
        __syncthreads();
        s[threadIdx.x] += t;
        __syncthreads();
    }
    if (gid < NROWS) g_rowptr[gid] = s[threadIdx.x] - v;   // exclusive, block-local
    if (threadIdx.x == SCAN_B - 1) g_partials[blockIdx.x] = s[threadIdx.x];
}

// ---------------------------------------------------------------------------
// K3b: each block sums the totals of all preceding blocks itself (98 ints),
//      then adds the base. Replaces the old scan2+scan3 pair.
// ---------------------------------------------------------------------------
__global__ void scan3_kernel()
{
    __shared__ int s[128];
    int t = threadIdx.x;
    if (t < 128) s[t] = (t < blockIdx.x && t < NBLK) ? g_partials[t] : 0;
    __syncthreads();
    #pragma unroll
    for (int off = 64; off > 0; off >>= 1) {
        if (t < off) s[t] += s[t + off];
        __syncthreads();
    }
    int base = s[0];

    int gid = blockIdx.x * SCAN_B + t;
    if (gid < NROWS) {
        int p = g_rowptr[gid] + base;
        g_rowptr[gid] = p;
        g_counts[gid] = p;     // scatter cursor
    }
}

// ---------------------------------------------------------------------------
// K4: scatter edges into CSR order, 4 edges per thread (MLP=4 on atomics).
// ---------------------------------------------------------------------------
__global__ void scatter_kernel(const int4* __restrict__ row4,
                               const int4* __restrict__ col4,
                               const float4* __restrict__ vals4)
{
    int i = blockIdx.x * blockDim.x + threadIdx.x;
    if (i < NNZ_E / 4) {
        int4   r = __ldg(row4 + i);
        int4   c = __ldg(col4 + i);
        float4 v = __ldg(vals4 + i);
        int p0 = atomicAdd(&g_counts[r.x], 1);
        int p1 = atomicAdd(&g_counts[r.y], 1);
        int p2 = atomicAdd(&g_counts[r.z], 1);
        int p3 = atomicAdd(&g_counts[r.w], 1);
        g_meta[p0] = make_int2(c.x, __float_as_int(v.x));
        g_meta[p1] = make_int2(c.y, __float_as_int(v.y));
        g_meta[p2] = make_int2(c.z, __float_as_int(v.z));
        g_meta[p3] = make_int2(c.w, __float_as_int(v.w));
    }
}

// ---------------------------------------------------------------------------
// Helper: fma 8 halves (uint4) scaled by v into acc[8].
// ---------------------------------------------------------------------------
__device__ __forceinline__ void fma8(float* acc, uint4 u, float v)
{
    float2 f0 = __half22float2(*reinterpret_cast<__half2*>(&u.x));
    float2 f1 = __half22float2(*reinterpret_cast<__half2*>(&u.y));
    float2 f2 = __half22float2(*reinterpret_cast<__half2*>(&u.z));
    float2 f3 = __half22float2(*reinterpret_cast<__half2*>(&u.w));
    acc[0] = fmaf(v, f0.x, acc[0]); acc[1] = fmaf(v, f0.y, acc[1]);
    acc[2] = fmaf(v, f1.x, acc[2]); acc[3] = fmaf(v, f1.y, acc[3]);
    acc[4] = fmaf(v, f2.x, acc[4]); acc[5] = fmaf(v, f2.y, acc[5]);
    acc[6] = fmaf(v, f3.x, acc[6]); acc[7] = fmaf(v, f3.y, acc[7]);
}

// ---------------------------------------------------------------------------
// K5: CSR SpMM with FP16 GATHERS (uint4 = 16B per thread), fp32 accumulation.
//     One warp per row; FOUR edge-groups of 8 threads; 2-deep pipeline
//     -> 8 edges in flight per warp, 8 LDGs per edge.
//     Reduce across groups with shfl_xor(8) + shfl_xor(16).
//   SRC: gather source selected device-side (0=g_embh, 1=g_e1h).
//   WRITE_H: also g_e1h[r,:] = fp16(y[r,:])   (layer 1 -> feeds layer 2)
//   FUSE:    also summed[r,:] = e0 + e1 + y   (layer 2)
// ---------------------------------------------------------------------------
template <int SRC, bool WRITE_H, bool FUSE>
__global__ void spmm_csr_kernel(float4* __restrict__ y,
                                const float4* __restrict__ e0,
                                const float4* __restrict__ e1,
                                float4* __restrict__ summed)
{
    const uint4* __restrict__ xh = (SRC == 0) ? g_embh : g_e1h;

    int warp = (blockIdx.x * blockDim.x + threadIdx.x) >> 5;
    int lane = threadIdx.x & 31;
    int grp  = lane >> 3;        // 0..3: edge group
    int j    = lane & 7;         // uint4 slot within the 128B fp16 row
    if (warp >= NROWS) return;
    int r = warp;

    int beg = g_rowptr[r];
    int end = g_rowptr[r + 1];

    float acc[8] = {0.f, 0.f, 0.f, 0.f, 0.f, 0.f, 0.f, 0.f};
    int e = beg + grp;           // this group's stream: e, e+4, e+8, ...
    // 2-deep: edges e and e+4 in flight -> 8 edges per warp concurrently
    for (; e + 4 < end; e += 8) {
        int2 m0 = __ldg(&g_meta[e]);
        int2 m1 = __ldg(&g_meta[e + 4]);
        uint4 u0 = __ldg(xh + (size_t)m0.x * 8 + j);
        uint4 u1 = __ldg(xh + (size_t)m1.x * 8 + j);
        fma8(acc, u0, __int_as_float(m0.y));
        fma8(acc, u1, __int_as_float(m1.y));
    }
    if (e < end) {
        int2 m0 = __ldg(&g_meta[e]);
        uint4 u0 = __ldg(xh + (size_t)m0.x * 8 + j);
        fma8(acc, u0, __int_as_float(m0.y));
    }

    // reduce the 4 groups: lanes l, l+8, l+16, l+24 hold partials of slot j
    #pragma unroll
    for (int k = 0; k < 8; k++) {
        acc[k] += __shfl_xor_sync(0xffffffffu, acc[k], 8);
        acc[k] += __shfl_xor_sync(0xffffffffu, acc[k], 16);
    }

    if (grp == 0) {
        // thread j holds floats 8j..8j+7 of output row r
        size_t o = (size_t)r * 16 + 2 * j;
        float4 lo = make_float4(acc[0], acc[1], acc[2], acc[3]);
        float4 hi = make_float4(acc[4], acc[5], acc[6], acc[7]);
        y[o]     = lo;
        y[o + 1] = hi;
        if (WRITE_H) {
            __half2 h0 = __floats2half2_rn(acc[0], acc[1]);
            __half2 h1 = __floats2half2_rn(acc[2], acc[3]);
            __half2 h2 = __floats2half2_rn(acc[4], acc[5]);
            __half2 h3 = __floats2half2_rn(acc[6], acc[7]);
            uint4 u;
            u.x = *reinterpret_cast<unsigned*>(&h0);
            u.y = *reinterpret_cast<unsigned*>(&h1);
            u.z = *reinterpret_cast<unsigned*>(&h2);
            u.w = *reinterpret_cast<unsigned*>(&h3);
            g_e1h[(size_t)r * 8 + j] = u;
        }
        if (FUSE) {
            float4 a0 = __ldg(e0 + o);
            float4 a1 = __ldg(e0 + o + 1);
            float4 b0 = __ldg(e1 + o);
            float4 b1 = __ldg(e1 + o + 1);
            float4 s0, s1;
            s0.x = a0.x + b0.x + lo.x; s0.y = a0.y + b0.y + lo.y;
            s0.z = a0.z + b0.z + lo.z; s0.w = a0.w + b0.w + lo.w;
            s1.x = a1.x + b1.x + hi.x; s1.y = a1.y + b1.y + hi.y;
            s1.z = a1.z + b1.z + hi.z; s1.w = a1.w + b1.w + hi.w;
            summed[o]     = s0;
            summed[o + 1] = s1;
        }
    }
}

// ---------------------------------------------------------------------------
// Launch sequence (default stream, graph-capturable, no allocations):
//   prep -> hist -> scan1 -> scan3 -> scatter -> spmm L1 -> spmm L2 (+sum)
// ---------------------------------------------------------------------------
extern "C" void kernel_launch(void* const* d_in, const int* in_sizes, int n_in,
                              void* d_out, int out_size)
{
    const int*   row  = (const int*)d_in[0];
    const int*   col  = (const int*)d_in[1];
    const float* vals = (const float*)d_in[2];
    const float* emb  = (const float*)d_in[3];

    float* out = (float*)d_out;
    float4* summed = (float4*)out;
    float4* e0 = (float4*)(out + (size_t)ND);
    float4* e1 = (float4*)(out + (size_t)2 * ND);
    float4* e2 = (float4*)(out + (size_t)3 * ND);

    const int TPB = 256;

    // K1: e0 copy + fp16 conversion + zero counts
    prep_kernel<<<(ND8 + TPB - 1) / TPB, TPB>>>((const float4*)emb, e0);

    // K2: histogram (4 edges per thread)
    hist_kernel<<<(NNZ_E / 4 + TPB - 1) / TPB, TPB>>>((const int4*)row);

    // K3: two-kernel exclusive scan -> rowptr + cursors
    scan1_kernel<<<NBLK, SCAN_B>>>();
    scan3_kernel<<<NBLK, SCAN_B>>>();

    // K4: scatter to CSR
    scatter_kernel<<<(NNZ_E / 4 + TPB - 1) / TPB, TPB>>>(
        (const int4*)row, (const int4*)col, (const float4*)vals);

    // K5/K6: warp per row, fp16 uint4 gathers
    const int WARPS_PER_BLOCK = TPB / 32;
    int spmm_blocks = (NROWS + WARPS_PER_BLOCK - 1) / WARPS_PER_BLOCK;

    // layer 1: e1 = A @ emb (gather g_embh), also g_e1h = fp16(e1)
    spmm_csr_kernel<0, true, false><<<spmm_blocks, TPB>>>(
        e1, nullptr, nullptr, nullptr);

    // layer 2: e2 = A @ e1 (gather g_e1h), fused summed = e0 + e1 + e2
    spmm_csr_kernel<1, false, true><<<spmm_blocks, TPB>>>(
        e2, (const float4*)e0, (const float4*)e1, summed);
}

// round 9
// speedup vs baseline: 1.1277x; 1.1277x over previous
#include <cuda_runtime.h>
#include <cuda_fp16.h>
#include <cstdint>

// Problem constants (match reference_code)
#define NROWS 100001
#define DIM   64
#define NNZ_E 3200000
#define ND    (NROWS * DIM)          // floats per segment
#define ND4   (ND / 4)               // float4 / uint2 granules per segment
#define SCAN_B 1024
#define NBLK  ((NROWS + SCAN_B - 1) / SCAN_B)   // 98

// ---------------------------------------------------------------------------
// Static device scratch. Referenced ONLY inside device code (R6 lesson:
// passing a __device__ symbol as a host-side kernel arg gives garbage).
// ---------------------------------------------------------------------------
__device__ int   g_counts[NROWS];       // histogram, then scatter cursors
__device__ int   g_rowptr[NROWS + 1];   // CSR row pointers (exclusive scan)
__device__ int   g_partials[NBLK];      // scan block totals
__device__ int2  g_meta[NNZ_E];         // CSR-ordered (col, val-bits), 25.6MB
__device__ uint2 g_embh[ND4];           // emb in fp16 (4 halves/uint2), 12.8MB
__device__ uint2 g_e1h[ND4];            // e1  in fp16, 12.8MB

// ---------------------------------------------------------------------------
// K0: zero histogram (must complete before prep_hist increments).
// ---------------------------------------------------------------------------
__global__ void zero_kernel()
{
    int i = blockIdx.x * blockDim.x + threadIdx.x;
    if (i < NROWS) g_counts[i] = 0;
    if (i == 0) g_rowptr[NROWS] = NNZ_E;
}

// ---------------------------------------------------------------------------
// K1: fused prep + hist.
//   i < ND4:     e0 = emb (fp32 copy), embh = fp16(emb)
//   i < NNZ/4:   histogram 4 edges (ND4 = 1.6M >= NNZ/4 = 800K)
// ---------------------------------------------------------------------------
__global__ void prep_hist_kernel(const float4* __restrict__ emb,
                                 float4* __restrict__ e0,
                                 const int4* __restrict__ row4)
{
    int i = blockIdx.x * blockDim.x + threadIdx.x;
    if (i < ND4) {
        float4 v = __ldg(emb + i);
        e0[i] = v;
        __half2 h0 = __floats2half2_rn(v.x, v.y);
        __half2 h1 = __floats2half2_rn(v.z, v.w);
        uint2 u;
        u.x = *reinterpret_cast<unsigned*>(&h0);
        u.y = *reinterpret_cast<unsigned*>(&h1);
        g_embh[i] = u;
    }
    if (i < NNZ_E / 4) {
        int4 r = __ldg(row4 + i);
        atomicAdd(&g_counts[r.x], 1);
        atomicAdd(&g_counts[r.y], 1);
        atomicAdd(&g_counts[r.z], 1);
        atomicAdd(&g_counts[r.w], 1);
    }
}

// ---------------------------------------------------------------------------
// K2: per-block exclusive scan of counts; block totals to g_partials.
// ---------------------------------------------------------------------------
__global__ void scan1_kernel()
{
    __shared__ int s[SCAN_B];
    int gid = blockIdx.x * SCAN_B + threadIdx.x;
    int v = (gid < NROWS) ? g_counts[gid] : 0;
    s[threadIdx.x] = v;
    __syncthreads();
    #pragma unroll
    for (int off = 1; off < SCAN_B; off <<= 1) {
        int t = (threadIdx.x >= off) ? s[threadIdx.x - off] : 0;
        __syncthreads();
        s[threadIdx.x] += t;
        __syncthreads();
    }
    if (gid < NROWS) g_rowptr[gid] = s[threadIdx.x] - v;   // exclusive, block-local
    if (threadIdx.x == SCAN_B - 1) g_partials[blockIdx.x] = s[threadIdx.x];
}

// ---------------------------------------------------------------------------
// K3: each block reduces totals of all preceding blocks (98 ints) itself,
//     then adds the base. Produces final rowptr + scatter cursors.
// ---------------------------------------------------------------------------
__global__ void scan3_kernel()
{
    __shared__ int s[128];
    int t = threadIdx.x;
    if (t < 128) s[t] = (t < blockIdx.x && t < NBLK) ? g_partials[t] : 0;
    __syncthreads();
    #pragma unroll
    for (int off = 64; off > 0; off >>= 1) {
        if (t < off) s[t] += s[t + off];
        __syncthreads();
    }
    int base = s[0];

    int gid = blockIdx.x * SCAN_B + t;
    if (gid < NROWS) {
        int p = g_rowptr[gid] + base;
        g_rowptr[gid] = p;
        g_counts[gid] = p;     // scatter cursor
    }
}

// ---------------------------------------------------------------------------
// K4: scatter edges into CSR order, 4 edges per thread (MLP=4 on atomics).
// ---------------------------------------------------------------------------
__global__ void scatter_kernel(const int4* __restrict__ row4,
                               const int4* __restrict__ col4,
                               const float4* __restrict__ vals4)
{
    int i = blockIdx.x * blockDim.x + threadIdx.x;
    if (i < NNZ_E / 4) {
        int4   r = __ldg(row4 + i);
        int4   c = __ldg(col4 + i);
        float4 v = __ldg(vals4 + i);
        int p0 = atomicAdd(&g_counts[r.x], 1);
        int p1 = atomicAdd(&g_counts[r.y], 1);
        int p2 = atomicAdd(&g_counts[r.z], 1);
        int p3 = atomicAdd(&g_counts[r.w], 1);
        g_meta[p0] = make_int2(c.x, __float_as_int(v.x));
        g_meta[p1] = make_int2(c.y, __float_as_int(v.y));
        g_meta[p2] = make_int2(c.z, __float_as_int(v.z));
        g_meta[p3] = make_int2(c.w, __float_as_int(v.w));
    }
}

// ---------------------------------------------------------------------------
// Helper: fma 4 halves (uint2) scaled by v into acc (float4).
// ---------------------------------------------------------------------------
__device__ __forceinline__ void fma4(float4& acc, uint2 u, float v)
{
    float2 a = __half22float2(*reinterpret_cast<__half2*>(&u.x));
    float2 b = __half22float2(*reinterpret_cast<__half2*>(&u.y));
    acc.x = fmaf(v, a.x, acc.x); acc.y = fmaf(v, a.y, acc.y);
    acc.z = fmaf(v, b.x, acc.z); acc.w = fmaf(v, b.y, acc.w);
}

// ---------------------------------------------------------------------------
// K5: CSR SpMM with FP16 GATHERS, fp32 accumulation (R7 structure).
//     One warp per row; half-warps take alternating edges; 3-DEEP pipeline
//     -> 6 edges in flight per warp. Reduce halves with shfl_xor(16).
//   SRC: gather source selected device-side (0=g_embh, 1=g_e1h).
//   WRITE_H: also g_e1h[r,:] = fp16(y[r,:])   (layer 1 -> feeds layer 2)
//   FUSE:    also summed[r,:] = e0 + e1 + y   (layer 2)
// ---------------------------------------------------------------------------
template <int SRC, bool WRITE_H, bool FUSE>
__global__ void spmm_csr_kernel(float4* __restrict__ y,
                                const float4* __restrict__ e0,
                                const float4* __restrict__ e1,
                                float4* __restrict__ summed)
{
    const uint2* __restrict__ xh = (SRC == 0) ? g_embh : g_e1h;

    int warp = (blockIdx.x * blockDim.x + threadIdx.x) >> 5;
    int lane = threadIdx.x & 31;
    int j    = lane & 15;        // uint2 slot within the 128B fp16 row
    int half = lane >> 4;        // 0 or 1: which edge of the pair
    if (warp >= NROWS) return;
    int r = warp;

    int beg = g_rowptr[r];
    int end = g_rowptr[r + 1];

    float4 acc = make_float4(0.f, 0.f, 0.f, 0.f);
    int e = beg + half;          // this thread's edge stream: e, e+2, e+4, ...

    // 3-deep: edges e, e+2, e+4 in flight -> 6 edges per warp concurrently
    for (; e + 4 < end; e += 6) {
        int2 m0 = __ldg(&g_meta[e]);
        int2 m1 = __ldg(&g_meta[e + 2]);
        int2 m2 = __ldg(&g_meta[e + 4]);
        uint2 u0 = __ldg(xh + (size_t)m0.x * 16 + j);
        uint2 u1 = __ldg(xh + (size_t)m1.x * 16 + j);
        uint2 u2 = __ldg(xh + (size_t)m2.x * 16 + j);
        fma4(acc, u0, __int_as_float(m0.y));
        fma4(acc, u1, __int_as_float(m1.y));
        fma4(acc, u2, __int_as_float(m2.y));
    }
    // 2-deep remainder
    if (e + 2 < end) {
        int2 m0 = __ldg(&g_meta[e]);
        int2 m1 = __ldg(&g_meta[e + 2]);
        uint2 u0 = __ldg(xh + (size_t)m0.x * 16 + j);
        uint2 u1 = __ldg(xh + (size_t)m1.x * 16 + j);
        fma4(acc, u0, __int_as_float(m0.y));
        fma4(acc, u1, __int_as_float(m1.y));
        e += 4;
    }
    if (e < end) {
        int2 m0 = __ldg(&g_meta[e]);
        uint2 u0 = __ldg(xh + (size_t)m0.x * 16 + j);
        fma4(acc, u0, __int_as_float(m0.y));
    }

    // combine the two half-warp partials
    acc.x += __shfl_xor_sync(0xffffffffu, acc.x, 16);
    acc.y += __shfl_xor_sync(0xffffffffu, acc.y, 16);
    acc.z += __shfl_xor_sync(0xffffffffu, acc.z, 16);
    acc.w += __shfl_xor_sync(0xffffffffu, acc.w, 16);

    if (half == 0) {
        size_t o = (size_t)r * 16 + j;
        y[o] = acc;
        if (WRITE_H) {
            __half2 h0 = __floats2half2_rn(acc.x, acc.y);
            __half2 h1 = __floats2half2_rn(acc.z, acc.w);
            uint2 u;
            u.x = *reinterpret_cast<unsigned*>(&h0);
            u.y = *reinterpret_cast<unsigned*>(&h1);
            g_e1h[o] = u;
        }
        if (FUSE) {
            float4 a = __ldg(e0 + o);
            float4 b = __ldg(e1 + o);
            float4 s;
            s.x = a.x + b.x + acc.x;
            s.y = a.y + b.y + acc.y;
            s.z = a.z + b.z + acc.z;
            s.w = a.w + b.w + acc.w;
            summed[o] = s;
        }
    }
}

// ---------------------------------------------------------------------------
// Launch sequence (default stream, graph-capturable, no allocations):
//   zero -> prep+hist -> scan1 -> scan3 -> scatter -> spmm L1 -> spmm L2
// ---------------------------------------------------------------------------
extern "C" void kernel_launch(void* const* d_in, const int* in_sizes, int n_in,
                              void* d_out, int out_size)
{
    const int*   row  = (const int*)d_in[0];
    const int*   col  = (const int*)d_in[1];
    const float* vals = (const float*)d_in[2];
    const float* emb  = (const float*)d_in[3];

    float* out = (float*)d_out;
    float4* summed = (float4*)out;
    float4* e0 = (float4*)(out + (size_t)ND);
    float4* e1 = (float4*)(out + (size_t)2 * ND);
    float4* e2 = (float4*)(out + (size_t)3 * ND);

    const int TPB = 256;

    // K0: zero counts
    zero_kernel<<<(NROWS + TPB - 1) / TPB, TPB>>>();

    // K1: e0 copy + fp16 conversion + histogram (fused)
    prep_hist_kernel<<<(ND4 + TPB - 1) / TPB, TPB>>>(
        (const float4*)emb, e0, (const int4*)row);

    // K2/K3: exclusive scan -> rowptr + cursors
    scan1_kernel<<<NBLK, SCAN_B>>>();
    scan3_kernel<<<NBLK, SCAN_B>>>();

    // K4: scatter to CSR
    scatter_kernel<<<(NNZ_E / 4 + TPB - 1) / TPB, TPB>>>(
        (const int4*)row, (const int4*)col, (const float4*)vals);

    // K5/K6: warp per row, fp16 uint2 gathers, 3-deep pipeline
    const int WARPS_PER_BLOCK = TPB / 32;
    int spmm_blocks = (NROWS + WARPS_PER_BLOCK - 1) / WARPS_PER_BLOCK;

    // layer 1: e1 = A @ emb (gather g_embh), also g_e1h = fp16(e1)
    spmm_csr_kernel<0, true, false><<<spmm_blocks, TPB>>>(
        e1, nullptr, nullptr, nullptr);

    // layer 2: e2 = A @ e1 (gather g_e1h), fused summed = e0 + e1 + e2
    spmm_csr_kernel<1, false, true><<<spmm_blocks, TPB>>>(
        e2, (const float4*)e0, (const float4*)e1, summed);
}